// round 5
// baseline (speedup 1.0000x reference)
#include <cuda_runtime.h>

#define KS   13
#define RAD  6
#define TW   32
#define TH   4            // 32x4 outputs per block, 1 per thread
#define PW   (TW + 2*RAD) // 44
#define PH   (TH + 2*RAD) // 16
#define IMH  256
#define IMW  256
#define NC   4
#define NB   2
#define NT   128

__device__ __forceinline__ float fast_ex2(float x) {
    float r; asm("ex2.approx.ftz.f32 %0, %1;" : "=f"(r) : "f"(x)); return r;
}

__global__ __launch_bounds__(NT, 8)
void bilateral13_v5(const float* __restrict__ x, float* __restrict__ out) {
    __shared__ float4 tile[PH][PW];   // sc * (u01, v01, u23, v23) basis
    __shared__ float  s_T[KS * KS];   // K2 * ((iy-6)^2 + (ix-6)^2)

    const int tid = threadIdx.x;      // 0..127
    const int b   = blockIdx.z;
    const int tx0 = blockIdx.x * TW;
    const int ty0 = blockIdx.y * TH;

    // shared exponent scale (sigma_color = sigma_space = 3):
    //   K2 = -0.5/9 * log2(e); normalization constant cancels in the ratio.
    const float K2 = (-0.5f / 9.0f) * 1.4426950408889634f;
    // pre-scale so that arg = T - (sc*d)^2  -> saves the d*d FMUL per tap
    const float SC = 0.28311592f;     // sqrt(-K2) = sqrt(0.5/9 * log2(e))

    // ---- spatial table ----
    for (int e = tid; e < KS * KS; e += NT) {
        const int iy = e / KS - RAD;
        const int ix = e % KS - RAD;
        s_T[e] = K2 * (float)(iy * iy + ix * ix);
    }

    // ---- cooperative load: reflect pad, (u,v) basis change, pre-scale -----
    const float* xb = x + (size_t)b * NC * IMH * IMW;
    #pragma unroll
    for (int it = 0; it < (PH * PW + NT - 1) / NT; it++) {
        int i = tid + it * NT;
        if (i < PH * PW) {
            int py = i / PW, px = i % PW;
            int gy = ty0 + py - RAD;
            int gx = tx0 + px - RAD;
            gy = (gy < 0) ? -gy : ((gy >= IMH) ? (2 * IMH - 2 - gy) : gy);
            gx = (gx < 0) ? -gx : ((gx >= IMW) ? (2 * IMW - 2 - gx) : gx);
            int g = gy * IMW + gx;
            float p0 = xb[0 * IMH * IMW + g];
            float p1 = xb[1 * IMH * IMW + g];
            float p2 = xb[2 * IMH * IMW + g];
            float p3 = xb[3 * IMH * IMW + g];
            float4 v;
            v.x = SC * (p0 + p1);   // sc*u01
            v.y = SC * (p0 - p1);   // sc*v01
            v.z = SC * (p2 + p3);   // sc*u23
            v.w = SC * (p2 - p3);   // sc*v23
            tile[py][px] = v;
        }
    }
    __syncthreads();

    // ---- per-thread: one output pixel ----
    const int lx = tid & (TW - 1);    // 0..31
    const int ly = tid >> 5;          // 0..3

    const float4 c = tile[ly + RAD][lx + RAD];

    float accU01 = 0.f, accV01 = 0.f, accU23 = 0.f, accV23 = 0.f, wsum = 0.f;

    #pragma unroll 1
    for (int iy = 0; iy < KS; iy++) {
        const float4* row  = &tile[ly + iy][lx];
        const float*  Trow = &s_T[iy * KS];
        #pragma unroll
        for (int ix = 0; ix < KS; ix++) {
            float4 p = row[ix];
            // |d0|+|d1| = max(|du01|, |dv01|)  (FADD x2 + FMNMX on ALU pipe)
            float m01 = fmaxf(fabsf(p.x - c.x), fabsf(p.y - c.y));
            float m23 = fmaxf(fabsf(p.z - c.z), fabsf(p.w - c.w));
            float d   = m01 + m23;                  // = sc * L1-distance
            float w = fast_ex2(fmaf(d, -d, Trow[ix]));  // T - (sc*d)^2
            wsum += w;
            accU01 = fmaf(w, p.x, accU01);
            accV01 = fmaf(w, p.y, accV01);
            accU23 = fmaf(w, p.z, accU23);
            accV23 = fmaf(w, p.w, accV23);
        }
    }

    // ---- epilogue: undo basis change + pre-scale, normalize ----
    const float hinv = __fdividef(0.5f, SC * wsum);
    float* ob = out + (size_t)b * NC * IMH * IMW;
    const int o = (ty0 + ly) * IMW + (tx0 + lx);
    ob[0 * IMH * IMW + o] = (accU01 + accV01) * hinv;
    ob[1 * IMH * IMW + o] = (accU01 - accV01) * hinv;
    ob[2 * IMH * IMW + o] = (accU23 + accV23) * hinv;
    ob[3 * IMH * IMW + o] = (accU23 - accV23) * hinv;
}

extern "C" void kernel_launch(void* const* d_in, const int* in_sizes, int n_in,
                              void* d_out, int out_size) {
    const float* x = (const float*)d_in[0];
    float* out = (float*)d_out;
    dim3 grid(IMW / TW, IMH / TH, NB);   // 8 x 64 x 2 = 1024 blocks
    bilateral13_v5<<<grid, NT>>>(x, out);
}